// round 14
// baseline (speedup 1.0000x reference)
#include <cuda_runtime.h>
#include <cuda_bf16.h>
#include <stdint.h>

// SparseMixerV2 forward — warp-private cp.async pipelines, HALF-ROW PER LANE.
//   sel = argmax(logits) (first occurrence)
//   keep_j iff l_j >= T,  T = m*0.8 (m>=0) else m*1.25   [exact mask closed form]
//   multiplier = (0.3333+0.6667) / sum_keep exp(l_j - m)
// rand_u provably dead (sel == argmax(masked_gates) always).
//
// 16-row / 4KB tiles, 2-deep ring per warp (8KB), 2 warps per 64-thread block
// (16KB static smem) -> 13 blocks/SM = 26 independent warp-pipelines (2.2x
// round-13's 12) to raise memory-level parallelism. Lanes 0-15 handle quads
// 0-7 of rows 0-15, lanes 16-31 quads 8-15 of the same rows; pair merge is
// 3 shuffles (max, sum, argmax-candidate min).

#define E 64
#define TPB 64
#define TILE 16
#define BUF_FLOATS (TILE * E)          // 1024 floats = 4KB
#define LOG2E 1.4426950408889634f

__device__ __forceinline__ void prefetch_tile(const float* __restrict__ logits,
                                              float* __restrict__ buf,
                                              int tile, int lane)
{
    const float4* g = reinterpret_cast<const float4*>(logits + (size_t)tile * TILE * E);
    #pragma unroll
    for (int i = 0; i < 8; i++) {
        int idx  = lane + i * 32;          // 256 float4 per 16-row tile
        int row  = idx >> 4;               // 0..15
        int col  = idx & 15;
        int slot = col ^ row;              // XOR swizzle (row < 16)
        uint32_t dst = (uint32_t)__cvta_generic_to_shared(buf + row * E + slot * 4);
        asm volatile("cp.async.cg.shared.global [%0], [%1], 16;"
                     :: "r"(dst), "l"(g + idx) : "memory");
    }
    asm volatile("cp.async.commit_group;" ::: "memory");
}

__global__ void __launch_bounds__(TPB)
sparsemixer_hr(const float* __restrict__ logits,
               float* __restrict__ out,      // [0,N): sel, [N,2N): mult, [2N]: 0
               int N, int out_size)
{
    __shared__ float smem[2][2][BUF_FLOATS];   // [warp][slot][..] = 16KB static
    const int lane = threadIdx.x & 31;
    const int w    = threadIdx.x >> 5;

    if (blockIdx.x == 0 && threadIdx.x == 0 && out_size > 2 * N)
        out[2 * N] = 0.0f;                     // balance_loss

    const int numTiles   = N / TILE;
    const int totalWarps = gridDim.x * 2;
    int tile = blockIdx.x * 2 + w;
    if (tile >= numTiles) return;

    prefetch_tile(logits, smem[w][0], tile, lane);

    const int r     = lane & 15;               // my row within tile
    const int cbase = (lane >> 4) << 3;        // my quad group: 0..7 or 8..15
    const uint32_t b0 = (uint32_t)__cvta_generic_to_shared(smem[w][0]);
    const uint32_t b1 = (uint32_t)__cvta_generic_to_shared(smem[w][1]);
    // pre-rotated row base: bits 4..7 = r, so addr = rowrot ^ (c<<4) de-swizzles
    const uint32_t rot = (uint32_t)r * 256u + ((uint32_t)r << 4);
    const uint32_t rowrot[2] = { b0 + rot, b1 + rot };

    int bufIdx = 0;
    for (; tile < numTiles; tile += totalWarps) {
        const int nextTile = tile + totalWarps;
        if (nextTile < numTiles) {
            prefetch_tile(logits, smem[w][bufIdx ^ 1], nextTile, lane);
            asm volatile("cp.async.wait_group 1;" ::: "memory");
        } else {
            asm volatile("cp.async.wait_group 0;" ::: "memory");
        }
        __syncwarp();

        // ---- gather my half-row: 8 LDS.128 (XOR address self-de-swizzles) ----
        float4 v[8];
        const uint32_t rb = rowrot[bufIdx];
        #pragma unroll
        for (int i = 0; i < 8; i++) {
            float4 tmp;
            asm volatile("ld.shared.v4.f32 {%0,%1,%2,%3}, [%4];"
                         : "=f"(tmp.x), "=f"(tmp.y), "=f"(tmp.z), "=f"(tmp.w)
                         : "r"(rb ^ ((uint32_t)(cbase + i) << 4)));
            v[i] = tmp;
        }

        // ---- per-quad maxes + half-row max, then pair merge ----
        float qm[8];
        #pragma unroll
        for (int i = 0; i < 8; i++)
            qm[i] = fmaxf(fmaxf(v[i].x, v[i].y), fmaxf(v[i].z, v[i].w));
        float ml = fmaxf(fmaxf(fmaxf(qm[0], qm[1]), fmaxf(qm[2], qm[3])),
                         fmaxf(fmaxf(qm[4], qm[5]), fmaxf(qm[6], qm[7])));
        const float m = fmaxf(ml, __shfl_xor_sync(0xffffffffu, ml, 16));

        const float T  = m * (m >= 0.0f ? 0.8f : 1.25f);   // keep iff x >= T
        const float c0 = -m * LOG2E;                        // exp(l-m)=ex2(l*log2e+c0)

        // ---- masked exp-sum over my 32 elements (2 chains), pair merge ----
        float sa = 0.0f, sb = 0.0f;
        #define SM_ELEM(S, X) {                                                  \
            const float x_ = (X);                                                \
            float ex_;                                                           \
            asm("ex2.approx.f32 %0, %1;" : "=f"(ex_) : "f"(fmaf(x_, LOG2E, c0)));\
            if (x_ >= T) S += ex_; }
        #pragma unroll
        for (int i = 0; i < 8; i += 2) {
            SM_ELEM(sa, v[i].x)   SM_ELEM(sa, v[i].y)
            SM_ELEM(sa, v[i].z)   SM_ELEM(sa, v[i].w)
            SM_ELEM(sb, v[i+1].x) SM_ELEM(sb, v[i+1].y)
            SM_ELEM(sb, v[i+1].z) SM_ELEM(sb, v[i+1].w)
        }
        #undef SM_ELEM
        float sl = sa + sb;
        const float s = sl + __shfl_xor_sync(0xffffffffu, sl, 16);

        // ---- argmax: smallest local quad attaining m (desc scan), then pair min ----
        int selq = 16;                          // sentinel: no match in my half
        #pragma unroll
        for (int j = 7; j >= 0; j--)
            if (qm[j] == m) selq = j;
        int cand = 1024;
        if (selq < 16) {
            float4 q;
            asm volatile("ld.shared.v4.f32 {%0,%1,%2,%3}, [%4];"
                         : "=f"(q.x), "=f"(q.y), "=f"(q.z), "=f"(q.w)
                         : "r"(rb ^ ((uint32_t)(cbase + selq) << 4)));
            int e = 3;
            if (q.z == m) e = 2;
            if (q.y == m) e = 1;
            if (q.x == m) e = 0;
            cand = 4 * (cbase + selq) + e;
        }
        const int sel = min(cand, __shfl_xor_sync(0xffffffffu, cand, 16));

        // ---- outputs: lanes<16 write sel, lanes>=16 write multiplier ----
        const int row = tile * TILE + r;
        const float mf1 = 0.3333f + 0.6667f;    // mask_for_one (always true-branch)
        if (lane < 16) out[row]     = (float)sel;
        else           out[N + row] = mf1 / s;

        __syncwarp();
        bufIdx ^= 1;
    }
}

extern "C" void kernel_launch(void* const* d_in, const int* in_sizes, int n_in,
                              void* d_out, int out_size)
{
    const float* logits = (const float*)d_in[0];   // d_in[1] = rand_u: dead
    float* out = (float*)d_out;

    const int N = in_sizes[0] / E;                 // 1048576
    const int numTiles = N / TILE;                 // 65536

    int blocks = 13 * 148;                         // 26 warp-pipelines/SM, 208KB smem
    if (blocks * 2 > numTiles) blocks = numTiles / 2;

    sparsemixer_hr<<<blocks, TPB>>>(logits, out, N, out_size);
}